// round 5
// baseline (speedup 1.0000x reference)
#include <cuda_runtime.h>
#include <cuda_bf16.h>
#include <math.h>
#include <stdint.h>

#define BATCH 16384
#define HDIM  1024
#define NJ    64

// ---------------------------------------------------------------------------
// Scratch (__device__ globals)
// ---------------------------------------------------------------------------
__device__ __nv_bfloat16 g_a_hi[BATCH * HDIM];
__device__ __nv_bfloat16 g_a_lo[BATCH * HDIM];
__device__ __nv_bfloat16 g_b_hi[BATCH * HDIM];
__device__ __nv_bfloat16 g_b_lo[BATCH * HDIM];
__device__ __nv_bfloat16 g_w2t_hi[HDIM * HDIM];
__device__ __nv_bfloat16 g_w2t_lo[HDIM * HDIM];
__device__ __nv_bfloat16 g_w3t_hi[HDIM * HDIM];
__device__ __nv_bfloat16 g_w3t_lo[HDIM * HDIM];
__device__ __nv_bfloat16 g_w4t_hi[256 * HDIM];
__device__ __nv_bfloat16 g_w4t_lo[256 * HDIM];
__device__ float g_joints[BATCH * 256];

// ---------------------------------------------------------------------------
// Helpers
// ---------------------------------------------------------------------------
__device__ __forceinline__ uint32_t smem_u32p(const void* p) {
    uint32_t a;
    asm("{ .reg .u64 t; cvta.to.shared.u64 t, %1; cvt.u32.u64 %0, t; }"
        : "=r"(a) : "l"(p));
    return a;
}

__device__ __forceinline__ void cp16(uint32_t dst, const void* src) {
    asm volatile("cp.async.cg.shared.global [%0], [%1], 16;"
                 :: "r"(dst), "l"(src) : "memory");
}

__device__ __forceinline__ void mma16816(float* c, const uint32_t* a,
                                         const uint32_t* b) {
    asm volatile(
        "mma.sync.aligned.m16n8k16.row.col.f32.bf16.bf16.f32 "
        "{%0,%1,%2,%3}, {%4,%5,%6,%7}, {%8,%9}, {%0,%1,%2,%3};"
        : "+f"(c[0]), "+f"(c[1]), "+f"(c[2]), "+f"(c[3])
        : "r"(a[0]), "r"(a[1]), "r"(a[2]), "r"(a[3]), "r"(b[0]), "r"(b[1]));
}

#define LDSM4(r0, r1, r2, r3, addr)                                            \
    asm volatile("ldmatrix.sync.aligned.m8n8.x4.shared.b16 {%0,%1,%2,%3}, [%4];" \
                 : "=r"(r0), "=r"(r1), "=r"(r2), "=r"(r3) : "r"(addr))

// ---------------------------------------------------------------------------
// Layer 1: h1 = lrelu(x @ W1 + b1), write bf16 hi/lo split. 4 outputs/thread.
// ---------------------------------------------------------------------------
__global__ __launch_bounds__(256)
void layer1_split_kernel(const float* __restrict__ x,
                         const float* __restrict__ W1,
                         const float* __restrict__ b1,
                         __nv_bfloat16* __restrict__ ohi,
                         __nv_bfloat16* __restrict__ olo) {
    int t = blockIdx.x * 256 + threadIdx.x;
    int row = t >> 8;
    int n = (t & 255) << 2;
    float x0 = x[row * 3 + 0], x1 = x[row * 3 + 1], x2 = x[row * 3 + 2];
    float4 w0 = *(const float4*)(W1 + 0 * HDIM + n);
    float4 w1 = *(const float4*)(W1 + 1 * HDIM + n);
    float4 w2 = *(const float4*)(W1 + 2 * HDIM + n);
    float4 bb = *(const float4*)(b1 + n);
    float v[4];
    v[0] = fmaf(x0, w0.x, fmaf(x1, w1.x, fmaf(x2, w2.x, bb.x)));
    v[1] = fmaf(x0, w0.y, fmaf(x1, w1.y, fmaf(x2, w2.y, bb.y)));
    v[2] = fmaf(x0, w0.z, fmaf(x1, w1.z, fmaf(x2, w2.z, bb.z)));
    v[3] = fmaf(x0, w0.w, fmaf(x1, w1.w, fmaf(x2, w2.w, bb.w)));
    __nv_bfloat162 hh[2], ll[2];
#pragma unroll
    for (int i = 0; i < 4; i++) v[i] = (v[i] >= 0.f) ? v[i] : 0.01f * v[i];
#pragma unroll
    for (int i = 0; i < 2; i++) {
        __nv_bfloat16 h0 = __float2bfloat16(v[2 * i]);
        __nv_bfloat16 h1 = __float2bfloat16(v[2 * i + 1]);
        hh[i].x = h0; hh[i].y = h1;
        ll[i].x = __float2bfloat16(v[2 * i] - __bfloat162float(h0));
        ll[i].y = __float2bfloat16(v[2 * i + 1] - __bfloat162float(h1));
    }
    size_t o = (size_t)row * HDIM + n;
    *(__nv_bfloat162*)(ohi + o) = hh[0];
    *(__nv_bfloat162*)(ohi + o + 2) = hh[1];
    *(__nv_bfloat162*)(olo + o) = ll[0];
    *(__nv_bfloat162*)(olo + o + 2) = ll[1];
}

// ---------------------------------------------------------------------------
// Transpose + split: W[K,N] fp32 -> Wt_hi/lo [N,K] bf16
// ---------------------------------------------------------------------------
__global__ void transpose_split_kernel(const float* __restrict__ W,
                                       __nv_bfloat16* __restrict__ Th,
                                       __nv_bfloat16* __restrict__ Tl,
                                       int K, int N) {
    __shared__ float s[32][33];
    int n0 = blockIdx.x * 32, k0 = blockIdx.y * 32;
    int tx = threadIdx.x, ty = threadIdx.y;
#pragma unroll
    for (int i = 0; i < 32; i += 8)
        s[ty + i][tx] = W[(size_t)(k0 + ty + i) * N + n0 + tx];
    __syncthreads();
#pragma unroll
    for (int i = 0; i < 32; i += 8) {
        float v = s[tx][ty + i];
        __nv_bfloat16 h = __float2bfloat16(v);
        size_t o = (size_t)(n0 + ty + i) * K + k0 + tx;
        Th[o] = h;
        Tl[o] = __float2bfloat16(v - __bfloat162float(h));
    }
}

// ---------------------------------------------------------------------------
// bf16 3-pass mma.sync GEMM, CTA 128(M)x256(N), warps 2x4, warp tile 64x64.
// K-chunk 64, 2-stage cp.async, ldmatrix fragments.
// A(hi/lo): [M,K] row-major bf16.  Bt(hi/lo): [Ntot,K] row-major bf16.
// ---------------------------------------------------------------------------
#define KC      64
#define PAD     144                   // 64 bf16 = 128B padded to 144B
#define A_TILE  (128 * PAD)           // 18432
#define B_TILE  (256 * PAD)           // 36864
#define STAGE   (2 * A_TILE + 2 * B_TILE)   // 110592
#define SMEM_TOT (2 * STAGE)          // 221184
#define OFF_AH  0
#define OFF_AL  A_TILE
#define OFF_BH  (2 * A_TILE)
#define OFF_BL  (2 * A_TILE + B_TILE)

__device__ __forceinline__ void load_A(uint32_t sdst,
                                       const __nv_bfloat16* __restrict__ g,
                                       int row0, int k0, int ldk, int tid) {
#pragma unroll
    for (int q = 0; q < 4; q++) {
        int e = q * 256 + tid;          // 0..1023
        int r = e >> 3, c = e & 7;
        const char* src = (const char*)(g + (size_t)(row0 + r) * ldk + k0) + c * 16;
        cp16(sdst + (uint32_t)(r * PAD + c * 16), src);
    }
}

__device__ __forceinline__ void load_B(uint32_t sdst,
                                       const __nv_bfloat16* __restrict__ g,
                                       int row0, int k0, int ldk, int tid) {
#pragma unroll
    for (int q = 0; q < 8; q++) {
        int e = q * 256 + tid;          // 0..2047
        int r = e >> 3, c = e & 7;
        const char* src = (const char*)(g + (size_t)(row0 + r) * ldk + k0) + c * 16;
        cp16(sdst + (uint32_t)(r * PAD + c * 16), src);
    }
}

template <int ACT>
__global__ __launch_bounds__(256)
void gemm_mma(const __nv_bfloat16* __restrict__ Ahi,
              const __nv_bfloat16* __restrict__ Alo,
              const __nv_bfloat16* __restrict__ Bhi,
              const __nv_bfloat16* __restrict__ Blo,
              const float* __restrict__ bias,
              __nv_bfloat16* __restrict__ Ohi,
              __nv_bfloat16* __restrict__ Olo,
              float* __restrict__ Of,
              int Ntot, int K) {
    extern __shared__ char smem[];
    const uint32_t sb = smem_u32p(smem);
    const int tid = threadIdx.x;
    const int wid = tid >> 5;
    const int lid = tid & 31;
    const int gid = lid >> 2;
    const int tig = lid & 3;
    const int wm = wid & 1;          // 0..1  (64-row halves)
    const int wn = wid >> 1;         // 0..3  (64-col quarters)
    const int m0 = blockIdx.y * 128;
    const int n0 = blockIdx.x * 256;

    // per-lane ldmatrix base offsets (row part), kk adds column bytes
    const uint32_t a_lane = (uint32_t)((wm * 64 + ((lid >> 3) & 1) * 8 + (lid & 7)) * PAD
                                       + ((lid >> 4) & 1) * 16);
    const uint32_t b_lane = (uint32_t)((wn * 64 + ((lid >> 4) & 1) * 8 + (lid & 7)) * PAD
                                       + ((lid >> 3) & 1) * 16);

    float c[4][8][4];
#pragma unroll
    for (int i = 0; i < 4; i++)
#pragma unroll
        for (int j = 0; j < 8; j++)
#pragma unroll
            for (int e = 0; e < 4; e++) c[i][j][e] = 0.0f;

    const int NCH = K / KC;

#pragma unroll
    for (int p = 0; p < 2; p++) {
        uint32_t st = sb + (uint32_t)p * STAGE;
        load_A(st + OFF_AH, Ahi, m0, p * KC, K, tid);
        load_A(st + OFF_AL, Alo, m0, p * KC, K, tid);
        load_B(st + OFF_BH, Bhi, n0, p * KC, K, tid);
        load_B(st + OFF_BL, Blo, n0, p * KC, K, tid);
        asm volatile("cp.async.commit_group;" ::: "memory");
    }

    for (int ch = 0; ch < NCH; ch++) {
        if (ch + 1 < NCH)
            asm volatile("cp.async.wait_group 1;" ::: "memory");
        else
            asm volatile("cp.async.wait_group 0;" ::: "memory");
        __syncthreads();

        const uint32_t st = sb + (uint32_t)(ch & 1) * STAGE;
        const uint32_t pAH = st + OFF_AH + a_lane;
        const uint32_t pAL = st + OFF_AL + a_lane;
        const uint32_t pBH = st + OFF_BH + b_lane;
        const uint32_t pBL = st + OFF_BL + b_lane;

#pragma unroll
        for (int kk = 0; kk < 4; kk++) {
            const uint32_t kb = (uint32_t)(kk * 32);
            uint32_t ah[4][4], bh[8][2], bl[8][2], al[4][4];
#pragma unroll
            for (int mt = 0; mt < 4; mt++)
                LDSM4(ah[mt][0], ah[mt][1], ah[mt][2], ah[mt][3],
                      pAH + (uint32_t)(mt * 16 * PAD) + kb);
#pragma unroll
            for (int p2 = 0; p2 < 4; p2++)
                LDSM4(bh[2 * p2][0], bh[2 * p2][1], bh[2 * p2 + 1][0], bh[2 * p2 + 1][1],
                      pBH + (uint32_t)(p2 * 16 * PAD) + kb);
#pragma unroll
            for (int mt = 0; mt < 4; mt++)
#pragma unroll
                for (int nt = 0; nt < 8; nt++)
                    mma16816(c[mt][nt], ah[mt], bh[nt]);
#pragma unroll
            for (int p2 = 0; p2 < 4; p2++)
                LDSM4(bl[2 * p2][0], bl[2 * p2][1], bl[2 * p2 + 1][0], bl[2 * p2 + 1][1],
                      pBL + (uint32_t)(p2 * 16 * PAD) + kb);
#pragma unroll
            for (int mt = 0; mt < 4; mt++)
#pragma unroll
                for (int nt = 0; nt < 8; nt++)
                    mma16816(c[mt][nt], ah[mt], bl[nt]);
#pragma unroll
            for (int mt = 0; mt < 4; mt++)
                LDSM4(al[mt][0], al[mt][1], al[mt][2], al[mt][3],
                      pAL + (uint32_t)(mt * 16 * PAD) + kb);
#pragma unroll
            for (int mt = 0; mt < 4; mt++)
#pragma unroll
                for (int nt = 0; nt < 8; nt++)
                    mma16816(c[mt][nt], al[mt], bh[nt]);
        }

        __syncthreads();
        if (ch + 2 < NCH) {
            uint32_t stn = sb + (uint32_t)(ch & 1) * STAGE;
            int k0 = (ch + 2) * KC;
            load_A(stn + OFF_AH, Ahi, m0, k0, K, tid);
            load_A(stn + OFF_AL, Alo, m0, k0, K, tid);
            load_B(stn + OFF_BH, Bhi, n0, k0, K, tid);
            load_B(stn + OFF_BL, Blo, n0, k0, K, tid);
            asm volatile("cp.async.commit_group;" ::: "memory");
        }
    }

    // Epilogue from registers
#pragma unroll
    for (int mt = 0; mt < 4; mt++) {
        int r0 = m0 + wm * 64 + mt * 16 + gid;
#pragma unroll
        for (int nt = 0; nt < 8; nt++) {
            int col = n0 + wn * 64 + nt * 8 + tig * 2;
            float bv0 = bias[col], bv1 = bias[col + 1];
            float v00 = c[mt][nt][0] + bv0;
            float v01 = c[mt][nt][1] + bv1;
            float v10 = c[mt][nt][2] + bv0;
            float v11 = c[mt][nt][3] + bv1;
            size_t o0 = (size_t)r0 * Ntot + col;
            size_t o1 = (size_t)(r0 + 8) * Ntot + col;
            if (ACT == 0) {
                v00 = (v00 >= 0.f) ? v00 : 0.01f * v00;
                v01 = (v01 >= 0.f) ? v01 : 0.01f * v01;
                v10 = (v10 >= 0.f) ? v10 : 0.01f * v10;
                v11 = (v11 >= 0.f) ? v11 : 0.01f * v11;
                __nv_bfloat162 hh0, hh1, ll0, ll1;
                hh0.x = __float2bfloat16(v00);
                hh0.y = __float2bfloat16(v01);
                hh1.x = __float2bfloat16(v10);
                hh1.y = __float2bfloat16(v11);
                ll0.x = __float2bfloat16(v00 - __bfloat162float(hh0.x));
                ll0.y = __float2bfloat16(v01 - __bfloat162float(hh0.y));
                ll1.x = __float2bfloat16(v10 - __bfloat162float(hh1.x));
                ll1.y = __float2bfloat16(v11 - __bfloat162float(hh1.y));
                *(__nv_bfloat162*)(Ohi + o0) = hh0;
                *(__nv_bfloat162*)(Ohi + o1) = hh1;
                *(__nv_bfloat162*)(Olo + o0) = ll0;
                *(__nv_bfloat162*)(Olo + o1) = ll1;
            } else {
                *(float2*)(Of + o0) = make_float2(tanhf(v00), tanhf(v01));
                *(float2*)(Of + o1) = make_float2(tanhf(v10), tanhf(v11));
            }
        }
    }
}

// ---------------------------------------------------------------------------
// FK chain
// ---------------------------------------------------------------------------
__global__ void fk_kernel(const float* __restrict__ joints,
                          float* __restrict__ out) {
    int b = blockIdx.x * blockDim.x + threadIdx.x;
    if (b >= BATCH) return;

    const float4* q4 = reinterpret_cast<const float4*>(joints + (size_t)b * 256);
    float* o = out + (size_t)b * NJ * 3;

    float r00 = 1.f, r01 = 0.f, r02 = 0.f;
    float r10 = 0.f, r11 = 1.f, r12 = 0.f;
    float r20 = 0.f, r21 = 0.f, r22 = 1.f;
    float t0 = 0.f, t1 = 0.f, t2 = 0.f;

    for (int j = 0; j < NJ; j++) {
        float4 q = q4[j];
        float w = q.x, x = q.y, y = q.z, z = q.w;
        float s = 2.0f / (w * w + x * x + y * y + z * z);

        float R00 = 1.0f - s * (y * y + z * z);
        float R01 = s * (x * y - z * w);
        float R02 = s * (x * z + y * w);
        float R10 = s * (x * y + z * w);
        float R11 = 1.0f - s * (x * x + z * z);
        float R12 = s * (y * z - x * w);
        float R20 = s * (x * z - y * w);
        float R21 = s * (y * z + x * w);
        float R22 = 1.0f - s * (x * x + y * y);

        float n00 = r00 * R00 + r01 * R10 + r02 * R20;
        float n01 = r00 * R01 + r01 * R11 + r02 * R21;
        float n02 = r00 * R02 + r01 * R12 + r02 * R22;
        float n10 = r10 * R00 + r11 * R10 + r12 * R20;
        float n11 = r10 * R01 + r11 * R11 + r12 * R21;
        float n12 = r10 * R02 + r11 * R12 + r12 * R22;
        float n20 = r20 * R00 + r21 * R10 + r22 * R20;
        float n21 = r20 * R01 + r21 * R11 + r22 * R21;
        float n22 = r20 * R02 + r21 * R12 + r22 * R22;

        t0 += n01; t1 += n11; t2 += n21;

        r00 = n00; r01 = n01; r02 = n02;
        r10 = n10; r11 = n11; r12 = n12;
        r20 = n20; r21 = n21; r22 = n22;

        o[j * 3 + 0] = t0;
        o[j * 3 + 1] = t1;
        o[j * 3 + 2] = t2;
    }
}

// ---------------------------------------------------------------------------
// Launch
// ---------------------------------------------------------------------------
extern "C" void kernel_launch(void* const* d_in, const int* in_sizes, int n_in,
                              void* d_out, int out_size) {
    const float* x  = (const float*)d_in[0];
    const float* W1 = (const float*)d_in[1];
    const float* b1 = (const float*)d_in[2];
    const float* W2 = (const float*)d_in[3];
    const float* b2 = (const float*)d_in[4];
    const float* W3 = (const float*)d_in[5];
    const float* b3 = (const float*)d_in[6];
    const float* W4 = (const float*)d_in[7];
    const float* b4 = (const float*)d_in[8];
    float* out = (float*)d_out;

    void* p;
#define SYM(v, s) cudaGetSymbolAddress(&p, s); auto* v = (__nv_bfloat16*)p;
    SYM(a_hi, g_a_hi); SYM(a_lo, g_a_lo);
    SYM(b_hi, g_b_hi); SYM(b_lo, g_b_lo);
    SYM(w2h, g_w2t_hi); SYM(w2l, g_w2t_lo);
    SYM(w3h, g_w3t_hi); SYM(w3l, g_w3t_lo);
    SYM(w4h, g_w4t_hi); SYM(w4l, g_w4t_lo);
#undef SYM
    cudaGetSymbolAddress(&p, g_joints);
    float* joints = (float*)p;

    cudaFuncSetAttribute(gemm_mma<0>,
                         cudaFuncAttributeMaxDynamicSharedMemorySize, SMEM_TOT);
    cudaFuncSetAttribute(gemm_mma<1>,
                         cudaFuncAttributeMaxDynamicSharedMemorySize, SMEM_TOT);

    // Weight transposes + splits
    {
        dim3 blk(32, 8);
        transpose_split_kernel<<<dim3(HDIM / 32, HDIM / 32), blk>>>(W2, w2h, w2l, HDIM, HDIM);
        transpose_split_kernel<<<dim3(HDIM / 32, HDIM / 32), blk>>>(W3, w3h, w3l, HDIM, HDIM);
        transpose_split_kernel<<<dim3(256 / 32,  HDIM / 32), blk>>>(W4, w4h, w4l, HDIM, 256);
    }

    // Layer 1
    layer1_split_kernel<<<(BATCH * HDIM) / 1024, 256>>>(x, W1, b1, a_hi, a_lo);

    // Layer 2: b = lrelu(a @ W2 + b2)
    gemm_mma<0><<<dim3(HDIM / 256, BATCH / 128), 256, SMEM_TOT>>>(
        a_hi, a_lo, w2h, w2l, b2, b_hi, b_lo, nullptr, HDIM, HDIM);
    // Layer 3: a = lrelu(b @ W3 + b3)
    gemm_mma<0><<<dim3(HDIM / 256, BATCH / 128), 256, SMEM_TOT>>>(
        b_hi, b_lo, w3h, w3l, b3, a_hi, a_lo, nullptr, HDIM, HDIM);
    // Layer 4: joints = tanh(a @ W4 + b4)
    gemm_mma<1><<<dim3(256 / 256, BATCH / 128), 256, SMEM_TOT>>>(
        a_hi, a_lo, w4h, w4l, b4, nullptr, nullptr, joints, 256, HDIM);

    // FK chain
    fk_kernel<<<BATCH / 256, 256>>>(joints, out);
}